// round 13
// baseline (speedup 1.0000x reference)
#include <cuda_runtime.h>
#include <cuda_fp16.h>
#include <math.h>

#define HH   256
#define WW   256
#define CCH  32
#define NB   16
#define TAPS 49
#define TO   64          // output tile (64x64)
#define SUS2 42          // su stride in half2 units (rows 76, 40 valid half2)
#define SDS2 38          // sd stride in half2 units (rows 70, 36 valid half2)

// Scratch (erosion output) stored as fp16 pairs — LOSSLESS: morph math is fp16.
__device__ __half2 g_scratch_h[(size_t)NB * CCH * HH * WW / 2];

__device__ __forceinline__ unsigned h2_as_u(__half2 h) {
    unsigned u;
    __builtin_memcpy(&u, &h, 4);
    return u;
}
__device__ __forceinline__ __half2 u_as_h2(unsigned u) {
    __half2 h;
    __builtin_memcpy(&h, &u, 4);
    return h;
}
// shifted pair: (hi of a, lo of b)
__device__ __forceinline__ __half2 shl_pair(__half2 a, __half2 b) {
    return u_as_h2(__byte_perm(h2_as_u(a), h2_as_u(b), 0x5432));
}

// ---------------------------------------------------------------------------
// Fused setup + convection + dilation + erosion, fp16x2 morph arithmetic.
// dilation = max_taps(u - kd)   (out-of-image u := -60000 ~ -inf in fp16)
// erosion  = min_taps(d + ke)   (out-of-image d := +60000 ~ +inf in fp16)
// ---------------------------------------------------------------------------
__global__ __launch_bounds__(256, 6) void morph_kernel(const float* __restrict__ x,
                                                       const float* __restrict__ cc,
                                                       const float* __restrict__ fdil,
                                                       const float* __restrict__ fero) {
    __shared__ __half2 su[76 * SUS2];
    __shared__ __half2 sd[70 * SDS2];
    __shared__ __half2 skd2[TAPS];
    __shared__ __half2 ske2[TAPS];
    __shared__ float   sbw[4];
    __shared__ int     sxy[2];

    int tid = threadIdx.x;
    int ch  = blockIdx.z & (CCH - 1);
    int b   = blockIdx.z >> 5;
    int Y0  = blockIdx.y * TO;
    int X0  = blockIdx.x * TO;

    // --- Phase 0: per-channel constants ---
    if (tid < TAPS) {
        float fdy = (float)(tid / 7 - 3);
        float fdx = (float)(tid % 7 - 3);
        float rho = sqrtf(fdx * fdx + fdy * fdy);
        float th  = atan2f(fdy, fdx);
        float b0 = cosf(th), b1 = sinf(th);
        float b2 = cosf(2.0f * th), b3 = sinf(2.0f * th);
        const float P  = 2.0f * 0.65f / (2.0f * 0.65f - 1.0f);   // 13/3
        const float NU = (2.0f * 0.65f - 1.0f) * powf(2.0f * 0.65f, -P);
        float s1 = fdil[ch*4+0]*b0 + fdil[ch*4+1]*b1 + fdil[ch*4+2]*b2 + fdil[ch*4+3]*b3;
        float kd = NU * powf(rho * expf(-s1), P);
        skd2[tid] = __float2half2_rn(fminf(kd, 60000.0f));
        float s2 = fero[ch*4+0]*b0 + fero[ch*4+1]*b1 + fero[ch*4+2]*b2 + fero[ch*4+3]*b3;
        float ke = NU * powf(rho * expf(-s2), P);
        ske2[tid] = __float2half2_rn(fminf(ke, 60000.0f));
    } else if (tid == 64) {
        float sx = cc[ch*2+0], sy = cc[ch*2+1];
        float fy = -sy, fx = -sx;
        float iy = floorf(fy), ix = floorf(fx);
        float wy = fy - iy,    wx = fx - ix;
        sxy[0] = (int)iy;
        sxy[1] = (int)ix;
        sbw[0] = (1.0f - wy) * (1.0f - wx);
        sbw[1] = (1.0f - wy) * wx;
        sbw[2] = wy * (1.0f - wx);
        sbw[3] = wy * wx;
    }
    __syncthreads();

    int   iy  = sxy[0], ix = sxy[1];
    float w00 = sbw[0], w01 = sbw[1], w10 = sbw[2], w11 = sbw[3];
    const float* __restrict__ plane = x + (size_t)(b * CCH + ch) * HH * WW;

    // --- Phase 1: convected u (fp32 bilinear), stored fp16x2.
    //     76 rows x 40 half2 (80 px), origin (Y0-6, X0-6). ---
    for (int idx = tid; idx < 76 * 40; idx += 256) {
        int ly = idx / 40, j = idx - ly * 40;
        int gy = Y0 - 6 + ly;
        float v[2];
        #pragma unroll
        for (int h = 0; h < 2; h++) {
            int gx = X0 - 6 + j * 2 + h;
            float vv = -60000.0f;
            if ((unsigned)gy < HH && (unsigned)gx < WW) {
                int y0 = min(max(gy + iy, 0), HH - 1);
                int y1 = min(y0 + 1, HH - 1);
                int x0 = min(max(gx + ix, 0), WW - 1);
                int x1 = min(x0 + 1, WW - 1);
                const float* r0 = plane + y0 * WW;
                const float* r1 = plane + y1 * WW;
                vv = w00 * r0[x0] + w01 * r0[x1] + w10 * r1[x0] + w11 * r1[x1];
            }
            v[h] = vv;
        }
        su[ly * SUS2 + j] = __floats2half2_rn(v[0], v[1]);
    }
    __syncthreads();

    const __half BIGH = __float2half_rn(60000.0f);

    // --- Phase 2: dilation, 70 rows x 36 half2 (72 px).
    //     Microtile 5 rows x 2 half2 (4 px): 14 x 18 = 252 items, single pass. ---
    if (tid < 14 * 18) {
        int miy  = tid / 18;
        int mixx = tid - miy * 18;
        int r0   = miy * 5;          // sd row base
        int c0h  = mixx * 2;         // half2 col base (window aligned)

        __half2 a[5][2];
        __half2 NEG2 = __float2half2_rn(-60000.0f);
        #pragma unroll
        for (int r = 0; r < 5; r++) { a[r][0] = NEG2; a[r][1] = NEG2; }

        #pragma unroll
        for (int wy = 0; wy < 11; wy++) {
            const __half2* rp = &su[(r0 + wy) * SUS2 + c0h];
            uint2 qa = *(const uint2*)rp;
            uint2 qb = *(const uint2*)(rp + 2);
            unsigned qc = *(const unsigned*)(rp + 4);
            __half2 p[5] = { u_as_h2(qa.x), u_as_h2(qa.y),
                             u_as_h2(qb.x), u_as_h2(qb.y), u_as_h2(qc) };
            __half2 s[4];
            #pragma unroll
            for (int i = 0; i < 4; i++) s[i] = shl_pair(p[i], p[i + 1]);

            #pragma unroll
            for (int dy = 0; dy < 7; dy++) {
                int r = wy - dy;
                if (r < 0 || r > 4) continue;       // compile-time pruned
                #pragma unroll
                for (int dx = 0; dx < 7; dx++) {
                    __half2 k2 = skd2[dy * 7 + dx];
                    #pragma unroll
                    for (int cx = 0; cx < 2; cx++) {
                        __half2 v = (dx & 1) ? s[cx + (dx >> 1)] : p[cx + (dx >> 1)];
                        a[r][cx] = __hmax2(a[r][cx], __hsub2(v, k2));
                    }
                }
            }
        }

        int gx0 = X0 - 3 + mixx * 4;
        #pragma unroll
        for (int r = 0; r < 5; r++) {
            int gy = Y0 - 3 + r0 + r;
            bool iny = (unsigned)gy < HH;
            #pragma unroll
            for (int cx = 0; cx < 2; cx++) {
                __half2 o = a[r][cx];
                bool va = iny && (unsigned)(gx0 + 2 * cx)     < WW;
                bool vb = iny && (unsigned)(gx0 + 2 * cx + 1) < WW;
                if (!va) o = __halves2half2(BIGH, __high2half(o));
                if (!vb) o = __halves2half2(__low2half(o), BIGH);
                sd[(r0 + r) * SDS2 + c0h + cx] = o;
            }
        }
    }
    __syncthreads();

    // --- Phase 3: erosion on 64x64 outputs. Microtile 4 rows x 2 half2:
    //     16 x 16 = 256 items, exactly 1/thread. Store fp16 (lossless). ---
    {
        int miy  = tid >> 4;
        int mixx = tid & 15;
        int r0   = miy * 4;
        int c0h  = mixx * 2;

        __half2 a[4][2];
        __half2 POS2 = __float2half2_rn(60000.0f);
        #pragma unroll
        for (int r = 0; r < 4; r++) { a[r][0] = POS2; a[r][1] = POS2; }

        #pragma unroll
        for (int wy = 0; wy < 10; wy++) {
            const __half2* rp = &sd[(r0 + wy) * SDS2 + c0h];
            uint2 qa = *(const uint2*)rp;
            uint2 qb = *(const uint2*)(rp + 2);
            unsigned qc = *(const unsigned*)(rp + 4);
            __half2 p[5] = { u_as_h2(qa.x), u_as_h2(qa.y),
                             u_as_h2(qb.x), u_as_h2(qb.y), u_as_h2(qc) };
            __half2 s[4];
            #pragma unroll
            for (int i = 0; i < 4; i++) s[i] = shl_pair(p[i], p[i + 1]);

            #pragma unroll
            for (int dy = 0; dy < 7; dy++) {
                int r = wy - dy;
                if (r < 0 || r > 3) continue;
                #pragma unroll
                for (int dx = 0; dx < 7; dx++) {
                    __half2 k2 = ske2[dy * 7 + dx];
                    #pragma unroll
                    for (int cx = 0; cx < 2; cx++) {
                        __half2 v = (dx & 1) ? s[cx + (dx >> 1)] : p[cx + (dx >> 1)];
                        a[r][cx] = __hmin2(a[r][cx], __hadd2(v, k2));
                    }
                }
            }
        }

        __half2* __restrict__ wout = g_scratch_h
                                   + (size_t)(b * CCH + ch) * (HH * WW / 2);
        #pragma unroll
        for (int r = 0; r < 4; r++) {
            uint2 sv = make_uint2(h2_as_u(a[r][0]), h2_as_u(a[r][1]));
            *(uint2*)(wout + (size_t)(Y0 + r0 + r) * (WW / 2) + (X0 >> 1) + mixx * 2) = sv;
        }
    }
}

// ---------------------------------------------------------------------------
// Channel mix: 2 pixels x 16 outputs per thread (half by blockIdx.z), half2
// loads, fp32 f32x2 FMA. Ring prefetch depth 8 (fully unrolled) for deeper
// latency coverage.
// ---------------------------------------------------------------------------
__global__ __launch_bounds__(256, 4) void mix_kernel(const float* __restrict__ wt,
                                                     float* __restrict__ out) {
    __shared__ unsigned long long sW[CCH * 16];
    int tid   = threadIdx.x;
    int ohalf = blockIdx.z;           // 0 or 1
    for (int i = tid; i < CCH * 16; i += 256) {
        int ci = i >> 4, o = i & 15;
        float w = wt[ci * CCH + ohalf * 16 + o];
        float2 p = make_float2(w, w);
        sW[i] = *reinterpret_cast<unsigned long long*>(&p);
    }
    __syncthreads();

    int b    = blockIdx.y;
    int pix2 = blockIdx.x * 256 + tid;            // half2 index (2 px/thread)
    const __half2* inp = g_scratch_h + (size_t)b * CCH * (HH * WW / 2) + pix2;
    float*         op  = out + (size_t)b * CCH * HH * WW
                             + (size_t)ohalf * 16 * HH * WW + (size_t)pix2 * 2;

    unsigned long long acc[16];
    #pragma unroll
    for (int o = 0; o < 16; o++) acc[o] = 0ull;

    unsigned vin[8];
    #pragma unroll
    for (int i = 0; i < 8; i++)
        vin[i] = *reinterpret_cast<const unsigned*>(inp + (size_t)i * (HH * WW / 2));

    #pragma unroll
    for (int i = 0; i < CCH; i++) {
        float2 f = __half22float2(u_as_h2(vin[i & 7]));
        if (i + 8 < CCH)
            vin[i & 7] = *reinterpret_cast<const unsigned*>(inp + (size_t)(i + 8) * (HH * WW / 2));
        unsigned long long v = *reinterpret_cast<unsigned long long*>(&f);
        const unsigned long long* wrow = &sW[i * 16];
        #pragma unroll
        for (int o = 0; o < 16; o++) {
            asm("fma.rn.f32x2 %0, %1, %2, %0;" : "+l"(acc[o]) : "l"(v), "l"(wrow[o]));
        }
    }

    #pragma unroll
    for (int o = 0; o < 16; o++)
        *reinterpret_cast<unsigned long long*>(op + (size_t)o * HH * WW) = acc[o];
}

// ---------------------------------------------------------------------------
extern "C" void kernel_launch(void* const* d_in, const int* in_sizes, int n_in,
                              void* d_out, int out_size) {
    const float* x  = (const float*)d_in[0];
    const float* c  = (const float*)d_in[1];
    const float* fd = (const float*)d_in[2];
    const float* fe = (const float*)d_in[3];
    const float* wt = (const float*)d_in[4];
    float* out = (float*)d_out;

    dim3 g1(WW / TO, HH / TO, NB * CCH);   // (4, 4, 512)
    morph_kernel<<<g1, 256>>>(x, c, fd, fe);

    dim3 g2((HH * WW) / 512, NB, 2);       // (128, 16, 2)
    mix_kernel<<<g2, 256>>>(wt, out);
}

// round 14
// speedup vs baseline: 1.3147x; 1.3147x over previous
#include <cuda_runtime.h>
#include <cuda_fp16.h>
#include <math.h>

#define HH   256
#define WW   256
#define CCH  32
#define NB   16
#define TAPS 49
#define TO   64          // output tile (64x64)
#define SUS2 42          // su stride in half2 units (rows 76, 40 valid half2)
#define SDS2 38          // sd stride in half2 units (rows 70, 36 valid half2)

// Scratch (erosion output) stored as fp16 pairs — LOSSLESS: morph math is fp16.
__device__ __half2 g_scratch_h[(size_t)NB * CCH * HH * WW / 2];

__device__ __forceinline__ unsigned h2_as_u(__half2 h) {
    unsigned u;
    __builtin_memcpy(&u, &h, 4);
    return u;
}
__device__ __forceinline__ __half2 u_as_h2(unsigned u) {
    __half2 h;
    __builtin_memcpy(&h, &u, 4);
    return h;
}
// shifted pair: (hi of a, lo of b)
__device__ __forceinline__ __half2 shl_pair(__half2 a, __half2 b) {
    return u_as_h2(__byte_perm(h2_as_u(a), h2_as_u(b), 0x5432));
}

// ---------------------------------------------------------------------------
// Fused setup + convection + dilation + erosion, fp16x2 morph arithmetic.
// dilation = max_taps(u - kd)   (out-of-image u := -60000 ~ -inf in fp16)
// erosion  = min_taps(d + ke)   (out-of-image d := +60000 ~ +inf in fp16)
// lb(256,5): 40 warps/SM, no spills (lb(256,6) measured to spill, R13).
// ---------------------------------------------------------------------------
__global__ __launch_bounds__(256, 5) void morph_kernel(const float* __restrict__ x,
                                                       const float* __restrict__ cc,
                                                       const float* __restrict__ fdil,
                                                       const float* __restrict__ fero) {
    __shared__ __half2 su[76 * SUS2];
    __shared__ __half2 sd[70 * SDS2];
    __shared__ __half2 skd2[TAPS];
    __shared__ __half2 ske2[TAPS];
    __shared__ float   sbw[4];
    __shared__ int     sxy[2];

    int tid = threadIdx.x;
    int ch  = blockIdx.z & (CCH - 1);
    int b   = blockIdx.z >> 5;
    int Y0  = blockIdx.y * TO;
    int X0  = blockIdx.x * TO;

    // --- Phase 0: per-channel constants ---
    if (tid < TAPS) {
        float fdy = (float)(tid / 7 - 3);
        float fdx = (float)(tid % 7 - 3);
        float rho = sqrtf(fdx * fdx + fdy * fdy);
        float th  = atan2f(fdy, fdx);
        float b0 = cosf(th), b1 = sinf(th);
        float b2 = cosf(2.0f * th), b3 = sinf(2.0f * th);
        const float P  = 2.0f * 0.65f / (2.0f * 0.65f - 1.0f);   // 13/3
        const float NU = (2.0f * 0.65f - 1.0f) * powf(2.0f * 0.65f, -P);
        float s1 = fdil[ch*4+0]*b0 + fdil[ch*4+1]*b1 + fdil[ch*4+2]*b2 + fdil[ch*4+3]*b3;
        float kd = NU * powf(rho * expf(-s1), P);
        skd2[tid] = __float2half2_rn(fminf(kd, 60000.0f));
        float s2 = fero[ch*4+0]*b0 + fero[ch*4+1]*b1 + fero[ch*4+2]*b2 + fero[ch*4+3]*b3;
        float ke = NU * powf(rho * expf(-s2), P);
        ske2[tid] = __float2half2_rn(fminf(ke, 60000.0f));
    } else if (tid == 64) {
        float sx = cc[ch*2+0], sy = cc[ch*2+1];
        float fy = -sy, fx = -sx;
        float iy = floorf(fy), ix = floorf(fx);
        float wy = fy - iy,    wx = fx - ix;
        sxy[0] = (int)iy;
        sxy[1] = (int)ix;
        sbw[0] = (1.0f - wy) * (1.0f - wx);
        sbw[1] = (1.0f - wy) * wx;
        sbw[2] = wy * (1.0f - wx);
        sbw[3] = wy * wx;
    }
    __syncthreads();

    int   iy  = sxy[0], ix = sxy[1];
    float w00 = sbw[0], w01 = sbw[1], w10 = sbw[2], w11 = sbw[3];
    const float* __restrict__ plane = x + (size_t)(b * CCH + ch) * HH * WW;

    // --- Phase 1: convected u (fp32 bilinear), stored fp16x2.
    //     76 rows x 40 half2 (80 px), origin (Y0-6, X0-6). ---
    for (int idx = tid; idx < 76 * 40; idx += 256) {
        int ly = idx / 40, j = idx - ly * 40;
        int gy = Y0 - 6 + ly;
        float v[2];
        #pragma unroll
        for (int h = 0; h < 2; h++) {
            int gx = X0 - 6 + j * 2 + h;
            float vv = -60000.0f;
            if ((unsigned)gy < HH && (unsigned)gx < WW) {
                int y0 = min(max(gy + iy, 0), HH - 1);
                int y1 = min(y0 + 1, HH - 1);
                int x0 = min(max(gx + ix, 0), WW - 1);
                int x1 = min(x0 + 1, WW - 1);
                const float* r0 = plane + y0 * WW;
                const float* r1 = plane + y1 * WW;
                vv = w00 * r0[x0] + w01 * r0[x1] + w10 * r1[x0] + w11 * r1[x1];
            }
            v[h] = vv;
        }
        su[ly * SUS2 + j] = __floats2half2_rn(v[0], v[1]);
    }
    __syncthreads();

    const __half BIGH = __float2half_rn(60000.0f);

    // --- Phase 2: dilation, 70 rows x 36 half2 (72 px).
    //     Microtile 5 rows x 2 half2 (4 px): 14 x 18 = 252 items, single pass. ---
    if (tid < 14 * 18) {
        int miy  = tid / 18;
        int mixx = tid - miy * 18;
        int r0   = miy * 5;          // sd row base
        int c0h  = mixx * 2;         // half2 col base (window aligned)

        __half2 a[5][2];
        __half2 NEG2 = __float2half2_rn(-60000.0f);
        #pragma unroll
        for (int r = 0; r < 5; r++) { a[r][0] = NEG2; a[r][1] = NEG2; }

        #pragma unroll
        for (int wy = 0; wy < 11; wy++) {
            const __half2* rp = &su[(r0 + wy) * SUS2 + c0h];
            uint2 qa = *(const uint2*)rp;
            uint2 qb = *(const uint2*)(rp + 2);
            unsigned qc = *(const unsigned*)(rp + 4);
            __half2 p[5] = { u_as_h2(qa.x), u_as_h2(qa.y),
                             u_as_h2(qb.x), u_as_h2(qb.y), u_as_h2(qc) };
            __half2 s[4];
            #pragma unroll
            for (int i = 0; i < 4; i++) s[i] = shl_pair(p[i], p[i + 1]);

            #pragma unroll
            for (int dy = 0; dy < 7; dy++) {
                int r = wy - dy;
                if (r < 0 || r > 4) continue;       // compile-time pruned
                #pragma unroll
                for (int dx = 0; dx < 7; dx++) {
                    __half2 k2 = skd2[dy * 7 + dx];
                    #pragma unroll
                    for (int cx = 0; cx < 2; cx++) {
                        __half2 v = (dx & 1) ? s[cx + (dx >> 1)] : p[cx + (dx >> 1)];
                        a[r][cx] = __hmax2(a[r][cx], __hsub2(v, k2));
                    }
                }
            }
        }

        int gx0 = X0 - 3 + mixx * 4;
        #pragma unroll
        for (int r = 0; r < 5; r++) {
            int gy = Y0 - 3 + r0 + r;
            bool iny = (unsigned)gy < HH;
            #pragma unroll
            for (int cx = 0; cx < 2; cx++) {
                __half2 o = a[r][cx];
                bool va = iny && (unsigned)(gx0 + 2 * cx)     < WW;
                bool vb = iny && (unsigned)(gx0 + 2 * cx + 1) < WW;
                if (!va) o = __halves2half2(BIGH, __high2half(o));
                if (!vb) o = __halves2half2(__low2half(o), BIGH);
                sd[(r0 + r) * SDS2 + c0h + cx] = o;
            }
        }
    }
    __syncthreads();

    // --- Phase 3: erosion on 64x64 outputs. Microtile 4 rows x 2 half2:
    //     16 x 16 = 256 items, exactly 1/thread. Store fp16 (lossless). ---
    {
        int miy  = tid >> 4;
        int mixx = tid & 15;
        int r0   = miy * 4;
        int c0h  = mixx * 2;

        __half2 a[4][2];
        __half2 POS2 = __float2half2_rn(60000.0f);
        #pragma unroll
        for (int r = 0; r < 4; r++) { a[r][0] = POS2; a[r][1] = POS2; }

        #pragma unroll
        for (int wy = 0; wy < 10; wy++) {
            const __half2* rp = &sd[(r0 + wy) * SDS2 + c0h];
            uint2 qa = *(const uint2*)rp;
            uint2 qb = *(const uint2*)(rp + 2);
            unsigned qc = *(const unsigned*)(rp + 4);
            __half2 p[5] = { u_as_h2(qa.x), u_as_h2(qa.y),
                             u_as_h2(qb.x), u_as_h2(qb.y), u_as_h2(qc) };
            __half2 s[4];
            #pragma unroll
            for (int i = 0; i < 4; i++) s[i] = shl_pair(p[i], p[i + 1]);

            #pragma unroll
            for (int dy = 0; dy < 7; dy++) {
                int r = wy - dy;
                if (r < 0 || r > 3) continue;
                #pragma unroll
                for (int dx = 0; dx < 7; dx++) {
                    __half2 k2 = ske2[dy * 7 + dx];
                    #pragma unroll
                    for (int cx = 0; cx < 2; cx++) {
                        __half2 v = (dx & 1) ? s[cx + (dx >> 1)] : p[cx + (dx >> 1)];
                        a[r][cx] = __hmin2(a[r][cx], __hadd2(v, k2));
                    }
                }
            }
        }

        __half2* __restrict__ wout = g_scratch_h
                                   + (size_t)(b * CCH + ch) * (HH * WW / 2);
        #pragma unroll
        for (int r = 0; r < 4; r++) {
            uint2 sv = make_uint2(h2_as_u(a[r][0]), h2_as_u(a[r][1]));
            *(uint2*)(wout + (size_t)(Y0 + r0 + r) * (WW / 2) + (X0 >> 1) + mixx * 2) = sv;
        }
    }
}

// ---------------------------------------------------------------------------
// Channel mix (R13-measured 72.9us): 2 pixels x 16 outputs per thread (half by
// blockIdx.z), half2 loads, fp32 f32x2 FMA, ring prefetch depth 8.
// ---------------------------------------------------------------------------
__global__ __launch_bounds__(256, 4) void mix_kernel(const float* __restrict__ wt,
                                                     float* __restrict__ out) {
    __shared__ unsigned long long sW[CCH * 16];
    int tid   = threadIdx.x;
    int ohalf = blockIdx.z;           // 0 or 1
    for (int i = tid; i < CCH * 16; i += 256) {
        int ci = i >> 4, o = i & 15;
        float w = wt[ci * CCH + ohalf * 16 + o];
        float2 p = make_float2(w, w);
        sW[i] = *reinterpret_cast<unsigned long long*>(&p);
    }
    __syncthreads();

    int b    = blockIdx.y;
    int pix2 = blockIdx.x * 256 + tid;            // half2 index (2 px/thread)
    const __half2* inp = g_scratch_h + (size_t)b * CCH * (HH * WW / 2) + pix2;
    float*         op  = out + (size_t)b * CCH * HH * WW
                             + (size_t)ohalf * 16 * HH * WW + (size_t)pix2 * 2;

    unsigned long long acc[16];
    #pragma unroll
    for (int o = 0; o < 16; o++) acc[o] = 0ull;

    unsigned vin[8];
    #pragma unroll
    for (int i = 0; i < 8; i++)
        vin[i] = *reinterpret_cast<const unsigned*>(inp + (size_t)i * (HH * WW / 2));

    #pragma unroll
    for (int i = 0; i < CCH; i++) {
        float2 f = __half22float2(u_as_h2(vin[i & 7]));
        if (i + 8 < CCH)
            vin[i & 7] = *reinterpret_cast<const unsigned*>(inp + (size_t)(i + 8) * (HH * WW / 2));
        unsigned long long v = *reinterpret_cast<unsigned long long*>(&f);
        const unsigned long long* wrow = &sW[i * 16];
        #pragma unroll
        for (int o = 0; o < 16; o++) {
            asm("fma.rn.f32x2 %0, %1, %2, %0;" : "+l"(acc[o]) : "l"(v), "l"(wrow[o]));
        }
    }

    #pragma unroll
    for (int o = 0; o < 16; o++)
        *reinterpret_cast<unsigned long long*>(op + (size_t)o * HH * WW) = acc[o];
}

// ---------------------------------------------------------------------------
extern "C" void kernel_launch(void* const* d_in, const int* in_sizes, int n_in,
                              void* d_out, int out_size) {
    const float* x  = (const float*)d_in[0];
    const float* c  = (const float*)d_in[1];
    const float* fd = (const float*)d_in[2];
    const float* fe = (const float*)d_in[3];
    const float* wt = (const float*)d_in[4];
    float* out = (float*)d_out;

    dim3 g1(WW / TO, HH / TO, NB * CCH);   // (4, 4, 512)
    morph_kernel<<<g1, 256>>>(x, c, fd, fe);

    dim3 g2((HH * WW) / 512, NB, 2);       // (128, 16, 2)
    mix_kernel<<<g2, 256>>>(wt, out);
}

// round 15
// speedup vs baseline: 1.4880x; 1.1318x over previous
#include <cuda_runtime.h>
#include <cuda_fp16.h>
#include <math.h>

#define HH   256
#define WW   256
#define CCH  32
#define NB   16
#define TAPS 49
#define TO   64          // output tile (64x64)
#define SUS2 42          // su stride in half2 units
#define SDS2 38          // sd stride in half2 units
#define SMP  264         // mix staging stride in halves (256 + 8 pad)

// Scratch (erosion output) stored as fp16 pairs — LOSSLESS: morph math is fp16.
__device__ __half2 g_scratch_h[(size_t)NB * CCH * HH * WW / 2];

__device__ __forceinline__ unsigned h2_as_u(__half2 h) {
    unsigned u;
    __builtin_memcpy(&u, &h, 4);
    return u;
}
__device__ __forceinline__ __half2 u_as_h2(unsigned u) {
    __half2 h;
    __builtin_memcpy(&h, &u, 4);
    return h;
}
__device__ __forceinline__ __half2 shl_pair(__half2 a, __half2 b) {
    return u_as_h2(__byte_perm(h2_as_u(a), h2_as_u(b), 0x5432));
}

// ---------------------------------------------------------------------------
// Morph kernel — unchanged from R14 (measured ~209us).
// ---------------------------------------------------------------------------
__global__ __launch_bounds__(256, 5) void morph_kernel(const float* __restrict__ x,
                                                       const float* __restrict__ cc,
                                                       const float* __restrict__ fdil,
                                                       const float* __restrict__ fero) {
    __shared__ __half2 su[76 * SUS2];
    __shared__ __half2 sd[70 * SDS2];
    __shared__ __half2 skd2[TAPS];
    __shared__ __half2 ske2[TAPS];
    __shared__ float   sbw[4];
    __shared__ int     sxy[2];

    int tid = threadIdx.x;
    int ch  = blockIdx.z & (CCH - 1);
    int b   = blockIdx.z >> 5;
    int Y0  = blockIdx.y * TO;
    int X0  = blockIdx.x * TO;

    if (tid < TAPS) {
        float fdy = (float)(tid / 7 - 3);
        float fdx = (float)(tid % 7 - 3);
        float rho = sqrtf(fdx * fdx + fdy * fdy);
        float th  = atan2f(fdy, fdx);
        float b0 = cosf(th), b1 = sinf(th);
        float b2 = cosf(2.0f * th), b3 = sinf(2.0f * th);
        const float P  = 2.0f * 0.65f / (2.0f * 0.65f - 1.0f);   // 13/3
        const float NU = (2.0f * 0.65f - 1.0f) * powf(2.0f * 0.65f, -P);
        float s1 = fdil[ch*4+0]*b0 + fdil[ch*4+1]*b1 + fdil[ch*4+2]*b2 + fdil[ch*4+3]*b3;
        float kd = NU * powf(rho * expf(-s1), P);
        skd2[tid] = __float2half2_rn(fminf(kd, 60000.0f));
        float s2 = fero[ch*4+0]*b0 + fero[ch*4+1]*b1 + fero[ch*4+2]*b2 + fero[ch*4+3]*b3;
        float ke = NU * powf(rho * expf(-s2), P);
        ske2[tid] = __float2half2_rn(fminf(ke, 60000.0f));
    } else if (tid == 64) {
        float sx = cc[ch*2+0], sy = cc[ch*2+1];
        float fy = -sy, fx = -sx;
        float iy = floorf(fy), ix = floorf(fx);
        float wy = fy - iy,    wx = fx - ix;
        sxy[0] = (int)iy;
        sxy[1] = (int)ix;
        sbw[0] = (1.0f - wy) * (1.0f - wx);
        sbw[1] = (1.0f - wy) * wx;
        sbw[2] = wy * (1.0f - wx);
        sbw[3] = wy * wx;
    }
    __syncthreads();

    int   iy  = sxy[0], ix = sxy[1];
    float w00 = sbw[0], w01 = sbw[1], w10 = sbw[2], w11 = sbw[3];
    const float* __restrict__ plane = x + (size_t)(b * CCH + ch) * HH * WW;

    for (int idx = tid; idx < 76 * 40; idx += 256) {
        int ly = idx / 40, j = idx - ly * 40;
        int gy = Y0 - 6 + ly;
        float v[2];
        #pragma unroll
        for (int h = 0; h < 2; h++) {
            int gx = X0 - 6 + j * 2 + h;
            float vv = -60000.0f;
            if ((unsigned)gy < HH && (unsigned)gx < WW) {
                int y0 = min(max(gy + iy, 0), HH - 1);
                int y1 = min(y0 + 1, HH - 1);
                int x0 = min(max(gx + ix, 0), WW - 1);
                int x1 = min(x0 + 1, WW - 1);
                const float* r0 = plane + y0 * WW;
                const float* r1 = plane + y1 * WW;
                vv = w00 * r0[x0] + w01 * r0[x1] + w10 * r1[x0] + w11 * r1[x1];
            }
            v[h] = vv;
        }
        su[ly * SUS2 + j] = __floats2half2_rn(v[0], v[1]);
    }
    __syncthreads();

    const __half BIGH = __float2half_rn(60000.0f);

    if (tid < 14 * 18) {
        int miy  = tid / 18;
        int mixx = tid - miy * 18;
        int r0   = miy * 5;
        int c0h  = mixx * 2;

        __half2 a[5][2];
        __half2 NEG2 = __float2half2_rn(-60000.0f);
        #pragma unroll
        for (int r = 0; r < 5; r++) { a[r][0] = NEG2; a[r][1] = NEG2; }

        #pragma unroll
        for (int wy = 0; wy < 11; wy++) {
            const __half2* rp = &su[(r0 + wy) * SUS2 + c0h];
            uint2 qa = *(const uint2*)rp;
            uint2 qb = *(const uint2*)(rp + 2);
            unsigned qc = *(const unsigned*)(rp + 4);
            __half2 p[5] = { u_as_h2(qa.x), u_as_h2(qa.y),
                             u_as_h2(qb.x), u_as_h2(qb.y), u_as_h2(qc) };
            __half2 s[4];
            #pragma unroll
            for (int i = 0; i < 4; i++) s[i] = shl_pair(p[i], p[i + 1]);

            #pragma unroll
            for (int dy = 0; dy < 7; dy++) {
                int r = wy - dy;
                if (r < 0 || r > 4) continue;
                #pragma unroll
                for (int dx = 0; dx < 7; dx++) {
                    __half2 k2 = skd2[dy * 7 + dx];
                    #pragma unroll
                    for (int cx = 0; cx < 2; cx++) {
                        __half2 v = (dx & 1) ? s[cx + (dx >> 1)] : p[cx + (dx >> 1)];
                        a[r][cx] = __hmax2(a[r][cx], __hsub2(v, k2));
                    }
                }
            }
        }

        int gx0 = X0 - 3 + mixx * 4;
        #pragma unroll
        for (int r = 0; r < 5; r++) {
            int gy = Y0 - 3 + r0 + r;
            bool iny = (unsigned)gy < HH;
            #pragma unroll
            for (int cx = 0; cx < 2; cx++) {
                __half2 o = a[r][cx];
                bool va = iny && (unsigned)(gx0 + 2 * cx)     < WW;
                bool vb = iny && (unsigned)(gx0 + 2 * cx + 1) < WW;
                if (!va) o = __halves2half2(BIGH, __high2half(o));
                if (!vb) o = __halves2half2(__low2half(o), BIGH);
                sd[(r0 + r) * SDS2 + c0h + cx] = o;
            }
        }
    }
    __syncthreads();

    {
        int miy  = tid >> 4;
        int mixx = tid & 15;
        int r0   = miy * 4;
        int c0h  = mixx * 2;

        __half2 a[4][2];
        __half2 POS2 = __float2half2_rn(60000.0f);
        #pragma unroll
        for (int r = 0; r < 4; r++) { a[r][0] = POS2; a[r][1] = POS2; }

        #pragma unroll
        for (int wy = 0; wy < 10; wy++) {
            const __half2* rp = &sd[(r0 + wy) * SDS2 + c0h];
            uint2 qa = *(const uint2*)rp;
            uint2 qb = *(const uint2*)(rp + 2);
            unsigned qc = *(const unsigned*)(rp + 4);
            __half2 p[5] = { u_as_h2(qa.x), u_as_h2(qa.y),
                             u_as_h2(qb.x), u_as_h2(qb.y), u_as_h2(qc) };
            __half2 s[4];
            #pragma unroll
            for (int i = 0; i < 4; i++) s[i] = shl_pair(p[i], p[i + 1]);

            #pragma unroll
            for (int dy = 0; dy < 7; dy++) {
                int r = wy - dy;
                if (r < 0 || r > 3) continue;
                #pragma unroll
                for (int dx = 0; dx < 7; dx++) {
                    __half2 k2 = ske2[dy * 7 + dx];
                    #pragma unroll
                    for (int cx = 0; cx < 2; cx++) {
                        __half2 v = (dx & 1) ? s[cx + (dx >> 1)] : p[cx + (dx >> 1)];
                        a[r][cx] = __hmin2(a[r][cx], __hadd2(v, k2));
                    }
                }
            }
        }

        __half2* __restrict__ wout = g_scratch_h
                                   + (size_t)(b * CCH + ch) * (HH * WW / 2);
        #pragma unroll
        for (int r = 0; r < 4; r++) {
            uint2 sv = make_uint2(h2_as_u(a[r][0]), h2_as_u(a[r][1]));
            *(uint2*)(wout + (size_t)(Y0 + r0 + r) * (WW / 2) + (X0 >> 1) + mixx * 2) = sv;
        }
    }
}

// ---------------------------------------------------------------------------
// Channel mix v6 — tensor-core GEMM. out[o,px] = sum_ch W[ch,o] * in[ch,px].
// A = W^T (fp16 fragments, built once in regs), B = scratch via ldmatrix.trans,
// D = fp32. Per block: 2048 px in 8 chunks of 256; per warp per chunk: 32 px.
// ---------------------------------------------------------------------------
__device__ __forceinline__ unsigned pack_h2f(float lo, float hi) {
    __half2 h = __floats2half2_rn(lo, hi);
    return h2_as_u(h);
}

__global__ __launch_bounds__(256, 4) void mix_mma_kernel(const float* __restrict__ wt,
                                                         float* __restrict__ out) {
    __shared__ __half sm[CCH * SMP];       // 32 x (256+8) halves = 16.5KB

    int tid  = threadIdx.x;
    int lane = tid & 31;
    int warp = tid >> 5;
    int b    = blockIdx.y;
    int g    = lane >> 2;                  // groupID
    int tg   = lane & 3;                   // thread-in-group

    // --- Build A fragments: A[r=out][c=ch] = W[ch][out], fp16. 2 kt x 2 ot. ---
    unsigned Af[2][2][4];
    #pragma unroll
    for (int kt = 0; kt < 2; kt++) {
        #pragma unroll
        for (int ot = 0; ot < 2; ot++) {
            int k0 = kt * 16 + 2 * tg;
            int o0 = ot * 16 + g;
            Af[kt][ot][0] = pack_h2f(wt[k0 * CCH + o0],       wt[(k0 + 1) * CCH + o0]);
            Af[kt][ot][1] = pack_h2f(wt[k0 * CCH + o0 + 8],   wt[(k0 + 1) * CCH + o0 + 8]);
            Af[kt][ot][2] = pack_h2f(wt[(k0 + 8) * CCH + o0], wt[(k0 + 9) * CCH + o0]);
            Af[kt][ot][3] = pack_h2f(wt[(k0 + 8) * CCH + o0 + 8], wt[(k0 + 9) * CCH + o0 + 8]);
        }
    }

    const __half2* src = g_scratch_h + (size_t)b * CCH * (HH * WW / 2);
    float* ob = out + (size_t)b * CCH * HH * WW;

    int ch_ld  = tid >> 3;                 // staging: each 8 lanes cover one ch row
    int seg_ld = (tid & 7) * 8;            // half units; + q*64 per q

    int px_block = blockIdx.x * 2048;

    for (int c = 0; c < 8; c++) {
        int px0 = px_block + c * 256;
        __syncthreads();                   // previous chunk's compute done
        // stage 32ch x 256px (fp16)
        {
            const __half2* grow = src + (size_t)ch_ld * (HH * WW / 2) + (px0 >> 1);
            #pragma unroll
            for (int q = 0; q < 4; q++) {
                uint4 v = *(const uint4*)(grow + ((seg_ld + q * 64) >> 1));
                *(uint4*)&sm[ch_ld * SMP + seg_ld + q * 64] = v;
            }
        }
        __syncthreads();

        int pxw = warp * 32;
        #pragma unroll
        for (int nt = 0; nt < 4; nt++) {
            int pxn = pxw + nt * 8;
            // B fragments: k-tile 0 (ch 0-15) and k-tile 1 (ch 16-31)
            unsigned b0a, b1a, b0b, b1b;
            unsigned a0 = (unsigned)__cvta_generic_to_shared(
                              &sm[(lane & 15) * SMP + pxn]);
            unsigned a1 = (unsigned)__cvta_generic_to_shared(
                              &sm[(16 + (lane & 15)) * SMP + pxn]);
            asm volatile("ldmatrix.sync.aligned.m8n8.x2.trans.shared.b16 {%0,%1}, [%2];"
                         : "=r"(b0a), "=r"(b1a) : "r"(a0));
            asm volatile("ldmatrix.sync.aligned.m8n8.x2.trans.shared.b16 {%0,%1}, [%2];"
                         : "=r"(b0b), "=r"(b1b) : "r"(a1));

            #pragma unroll
            for (int ot = 0; ot < 2; ot++) {
                float d0 = 0.f, d1 = 0.f, d2 = 0.f, d3 = 0.f;
                asm volatile(
                    "mma.sync.aligned.m16n8k16.row.col.f32.f16.f16.f32 "
                    "{%0,%1,%2,%3}, {%4,%5,%6,%7}, {%8,%9}, {%0,%1,%2,%3};"
                    : "+f"(d0), "+f"(d1), "+f"(d2), "+f"(d3)
                    : "r"(Af[0][ot][0]), "r"(Af[0][ot][1]),
                      "r"(Af[0][ot][2]), "r"(Af[0][ot][3]),
                      "r"(b0a), "r"(b1a));
                asm volatile(
                    "mma.sync.aligned.m16n8k16.row.col.f32.f16.f16.f32 "
                    "{%0,%1,%2,%3}, {%4,%5,%6,%7}, {%8,%9}, {%0,%1,%2,%3};"
                    : "+f"(d0), "+f"(d1), "+f"(d2), "+f"(d3)
                    : "r"(Af[1][ot][0]), "r"(Af[1][ot][1]),
                      "r"(Af[1][ot][2]), "r"(Af[1][ot][3]),
                      "r"(b0b), "r"(b1b));

                int px = px0 + pxn + 2 * tg;
                int o0 = ot * 16 + g;
                *(float2*)(ob + (size_t)o0 * (HH * WW) + px)       = make_float2(d0, d1);
                *(float2*)(ob + (size_t)(o0 + 8) * (HH * WW) + px) = make_float2(d2, d3);
            }
        }
    }
}

// ---------------------------------------------------------------------------
extern "C" void kernel_launch(void* const* d_in, const int* in_sizes, int n_in,
                              void* d_out, int out_size) {
    const float* x  = (const float*)d_in[0];
    const float* c  = (const float*)d_in[1];
    const float* fd = (const float*)d_in[2];
    const float* fe = (const float*)d_in[3];
    const float* wt = (const float*)d_in[4];
    float* out = (float*)d_out;

    dim3 g1(WW / TO, HH / TO, NB * CCH);   // (4, 4, 512)
    morph_kernel<<<g1, 256>>>(x, c, fd, fe);

    dim3 g2(32, NB);                       // 2048 px per block
    mix_mma_kernel<<<g2, 256>>>(wt, out);
}

// round 16
// speedup vs baseline: 1.5483x; 1.0405x over previous
#include <cuda_runtime.h>
#include <cuda_fp16.h>
#include <math.h>

#define HH   256
#define WW   256
#define CCH  32
#define NB   16
#define TAPS 49
#define TO   64          // output tile (64x64)
#define SUS2 42          // su stride in half2 units
#define SDS2 38          // sd stride in half2 units
#define SMP  264         // mix staging stride in halves (256 + 8 pad)

// Scratch (erosion output) stored as fp16 pairs — LOSSLESS: morph math is fp16.
__device__ __half2 g_scratch_h[(size_t)NB * CCH * HH * WW / 2];

__device__ __forceinline__ unsigned h2_as_u(__half2 h) {
    unsigned u;
    __builtin_memcpy(&u, &h, 4);
    return u;
}
__device__ __forceinline__ __half2 u_as_h2(unsigned u) {
    __half2 h;
    __builtin_memcpy(&h, &u, 4);
    return h;
}
__device__ __forceinline__ __half2 shl_pair(__half2 a, __half2 b) {
    return u_as_h2(__byte_perm(h2_as_u(a), h2_as_u(b), 0x5432));
}

// ---------------------------------------------------------------------------
// Morph kernel (lb(256,5), measured ~209us). Phase 1 fully unrolled for MLP.
// ---------------------------------------------------------------------------
__global__ __launch_bounds__(256, 5) void morph_kernel(const float* __restrict__ x,
                                                       const float* __restrict__ cc,
                                                       const float* __restrict__ fdil,
                                                       const float* __restrict__ fero) {
    __shared__ __half2 su[76 * SUS2];
    __shared__ __half2 sd[70 * SDS2];
    __shared__ __half2 skd2[TAPS];
    __shared__ __half2 ske2[TAPS];
    __shared__ float   sbw[4];
    __shared__ int     sxy[2];

    int tid = threadIdx.x;
    int ch  = blockIdx.z & (CCH - 1);
    int b   = blockIdx.z >> 5;
    int Y0  = blockIdx.y * TO;
    int X0  = blockIdx.x * TO;

    if (tid < TAPS) {
        float fdy = (float)(tid / 7 - 3);
        float fdx = (float)(tid % 7 - 3);
        float rho = sqrtf(fdx * fdx + fdy * fdy);
        float th  = atan2f(fdy, fdx);
        float b0 = cosf(th), b1 = sinf(th);
        float b2 = cosf(2.0f * th), b3 = sinf(2.0f * th);
        const float P  = 2.0f * 0.65f / (2.0f * 0.65f - 1.0f);   // 13/3
        const float NU = (2.0f * 0.65f - 1.0f) * powf(2.0f * 0.65f, -P);
        float s1 = fdil[ch*4+0]*b0 + fdil[ch*4+1]*b1 + fdil[ch*4+2]*b2 + fdil[ch*4+3]*b3;
        float kd = NU * powf(rho * expf(-s1), P);
        skd2[tid] = __float2half2_rn(fminf(kd, 60000.0f));
        float s2 = fero[ch*4+0]*b0 + fero[ch*4+1]*b1 + fero[ch*4+2]*b2 + fero[ch*4+3]*b3;
        float ke = NU * powf(rho * expf(-s2), P);
        ske2[tid] = __float2half2_rn(fminf(ke, 60000.0f));
    } else if (tid == 64) {
        float sx = cc[ch*2+0], sy = cc[ch*2+1];
        float fy = -sy, fx = -sx;
        float iy = floorf(fy), ix = floorf(fx);
        float wy = fy - iy,    wx = fx - ix;
        sxy[0] = (int)iy;
        sxy[1] = (int)ix;
        sbw[0] = (1.0f - wy) * (1.0f - wx);
        sbw[1] = (1.0f - wy) * wx;
        sbw[2] = wy * (1.0f - wx);
        sbw[3] = wy * wx;
    }
    __syncthreads();

    int   iy  = sxy[0], ix = sxy[1];
    float w00 = sbw[0], w01 = sbw[1], w10 = sbw[2], w11 = sbw[3];
    const float* __restrict__ plane = x + (size_t)(b * CCH + ch) * HH * WW;

    // Phase 1: convected u (fp32 bilinear) -> fp16x2 smem. 76 x 40 half2.
    // Fully unrolled (12 iters) so ptxas can batch the global loads (MLP up).
    #pragma unroll
    for (int it = 0; it < 12; it++) {
        int idx = tid + it * 256;
        if (idx < 76 * 40) {
            int ly = idx / 40, j = idx - ly * 40;
            int gy = Y0 - 6 + ly;
            float v[2];
            #pragma unroll
            for (int h = 0; h < 2; h++) {
                int gx = X0 - 6 + j * 2 + h;
                float vv = -60000.0f;
                if ((unsigned)gy < HH && (unsigned)gx < WW) {
                    int y0 = min(max(gy + iy, 0), HH - 1);
                    int y1 = min(y0 + 1, HH - 1);
                    int x0 = min(max(gx + ix, 0), WW - 1);
                    int x1 = min(x0 + 1, WW - 1);
                    const float* r0 = plane + y0 * WW;
                    const float* r1 = plane + y1 * WW;
                    vv = w00 * r0[x0] + w01 * r0[x1] + w10 * r1[x0] + w11 * r1[x1];
                }
                v[h] = vv;
            }
            su[ly * SUS2 + j] = __floats2half2_rn(v[0], v[1]);
        }
    }
    __syncthreads();

    const __half BIGH = __float2half_rn(60000.0f);

    if (tid < 14 * 18) {
        int miy  = tid / 18;
        int mixx = tid - miy * 18;
        int r0   = miy * 5;
        int c0h  = mixx * 2;

        __half2 a[5][2];
        __half2 NEG2 = __float2half2_rn(-60000.0f);
        #pragma unroll
        for (int r = 0; r < 5; r++) { a[r][0] = NEG2; a[r][1] = NEG2; }

        #pragma unroll
        for (int wy = 0; wy < 11; wy++) {
            const __half2* rp = &su[(r0 + wy) * SUS2 + c0h];
            uint2 qa = *(const uint2*)rp;
            uint2 qb = *(const uint2*)(rp + 2);
            unsigned qc = *(const unsigned*)(rp + 4);
            __half2 p[5] = { u_as_h2(qa.x), u_as_h2(qa.y),
                             u_as_h2(qb.x), u_as_h2(qb.y), u_as_h2(qc) };
            __half2 s[4];
            #pragma unroll
            for (int i = 0; i < 4; i++) s[i] = shl_pair(p[i], p[i + 1]);

            #pragma unroll
            for (int dy = 0; dy < 7; dy++) {
                int r = wy - dy;
                if (r < 0 || r > 4) continue;
                #pragma unroll
                for (int dx = 0; dx < 7; dx++) {
                    __half2 k2 = skd2[dy * 7 + dx];
                    #pragma unroll
                    for (int cx = 0; cx < 2; cx++) {
                        __half2 v = (dx & 1) ? s[cx + (dx >> 1)] : p[cx + (dx >> 1)];
                        a[r][cx] = __hmax2(a[r][cx], __hsub2(v, k2));
                    }
                }
            }
        }

        int gx0 = X0 - 3 + mixx * 4;
        #pragma unroll
        for (int r = 0; r < 5; r++) {
            int gy = Y0 - 3 + r0 + r;
            bool iny = (unsigned)gy < HH;
            #pragma unroll
            for (int cx = 0; cx < 2; cx++) {
                __half2 o = a[r][cx];
                bool va = iny && (unsigned)(gx0 + 2 * cx)     < WW;
                bool vb = iny && (unsigned)(gx0 + 2 * cx + 1) < WW;
                if (!va) o = __halves2half2(BIGH, __high2half(o));
                if (!vb) o = __halves2half2(__low2half(o), BIGH);
                sd[(r0 + r) * SDS2 + c0h + cx] = o;
            }
        }
    }
    __syncthreads();

    {
        int miy  = tid >> 4;
        int mixx = tid & 15;
        int r0   = miy * 4;
        int c0h  = mixx * 2;

        __half2 a[4][2];
        __half2 POS2 = __float2half2_rn(60000.0f);
        #pragma unroll
        for (int r = 0; r < 4; r++) { a[r][0] = POS2; a[r][1] = POS2; }

        #pragma unroll
        for (int wy = 0; wy < 10; wy++) {
            const __half2* rp = &sd[(r0 + wy) * SDS2 + c0h];
            uint2 qa = *(const uint2*)rp;
            uint2 qb = *(const uint2*)(rp + 2);
            unsigned qc = *(const unsigned*)(rp + 4);
            __half2 p[5] = { u_as_h2(qa.x), u_as_h2(qa.y),
                             u_as_h2(qb.x), u_as_h2(qb.y), u_as_h2(qc) };
            __half2 s[4];
            #pragma unroll
            for (int i = 0; i < 4; i++) s[i] = shl_pair(p[i], p[i + 1]);

            #pragma unroll
            for (int dy = 0; dy < 7; dy++) {
                int r = wy - dy;
                if (r < 0 || r > 3) continue;
                #pragma unroll
                for (int dx = 0; dx < 7; dx++) {
                    __half2 k2 = ske2[dy * 7 + dx];
                    #pragma unroll
                    for (int cx = 0; cx < 2; cx++) {
                        __half2 v = (dx & 1) ? s[cx + (dx >> 1)] : p[cx + (dx >> 1)];
                        a[r][cx] = __hmin2(a[r][cx], __hadd2(v, k2));
                    }
                }
            }
        }

        __half2* __restrict__ wout = g_scratch_h
                                   + (size_t)(b * CCH + ch) * (HH * WW / 2);
        #pragma unroll
        for (int r = 0; r < 4; r++) {
            uint2 sv = make_uint2(h2_as_u(a[r][0]), h2_as_u(a[r][1]));
            *(uint2*)(wout + (size_t)(Y0 + r0 + r) * (WW / 2) + (X0 >> 1) + mixx * 2) = sv;
        }
    }
}

// ---------------------------------------------------------------------------
// Channel mix v7 — tensor-core GEMM + cp.async double-buffered staging.
// ---------------------------------------------------------------------------
__device__ __forceinline__ unsigned pack_h2f(float lo, float hi) {
    __half2 h = __floats2half2_rn(lo, hi);
    return h2_as_u(h);
}

__global__ __launch_bounds__(256, 4) void mix_mma_kernel(const float* __restrict__ wt,
                                                         float* __restrict__ out) {
    __shared__ __half sm[2][CCH * SMP];    // 2 x 16.5KB

    int tid  = threadIdx.x;
    int lane = tid & 31;
    int warp = tid >> 5;
    int b    = blockIdx.y;
    int g    = lane >> 2;
    int tg   = lane & 3;

    // A fragments: A[r=out][c=ch] = W[ch][out], fp16. 2 kt x 2 ot.
    unsigned Af[2][2][4];
    #pragma unroll
    for (int kt = 0; kt < 2; kt++) {
        #pragma unroll
        for (int ot = 0; ot < 2; ot++) {
            int k0 = kt * 16 + 2 * tg;
            int o0 = ot * 16 + g;
            Af[kt][ot][0] = pack_h2f(wt[k0 * CCH + o0],       wt[(k0 + 1) * CCH + o0]);
            Af[kt][ot][1] = pack_h2f(wt[k0 * CCH + o0 + 8],   wt[(k0 + 1) * CCH + o0 + 8]);
            Af[kt][ot][2] = pack_h2f(wt[(k0 + 8) * CCH + o0], wt[(k0 + 9) * CCH + o0]);
            Af[kt][ot][3] = pack_h2f(wt[(k0 + 8) * CCH + o0 + 8], wt[(k0 + 9) * CCH + o0 + 8]);
        }
    }

    const __half2* src = g_scratch_h + (size_t)b * CCH * (HH * WW / 2);
    float* ob = out + (size_t)b * CCH * HH * WW;

    int ch_ld  = tid >> 3;
    int seg_ld = (tid & 7) * 8;            // half units (16B per cp.async)
    int px_block = blockIdx.x * 2048;

    // Stage chunk 0 into buffer 0.
    {
        const __half2* grow = src + (size_t)ch_ld * (HH * WW / 2) + (px_block >> 1);
        unsigned dst = (unsigned)__cvta_generic_to_shared(&sm[0][ch_ld * SMP + seg_ld]);
        #pragma unroll
        for (int q = 0; q < 4; q++)
            asm volatile("cp.async.cg.shared.global [%0], [%1], 16;" ::
                         "r"(dst + q * 128),
                         "l"((const void*)(grow + ((seg_ld + q * 64) >> 1))) : "memory");
        asm volatile("cp.async.commit_group;" ::: "memory");
    }

    #pragma unroll 1
    for (int c = 0; c < 8; c++) {
        if (c < 7) {
            // Stage chunk c+1 into the other buffer (its previous contents were
            // consumed in iteration c-1 and fenced by the trailing syncthreads).
            int pxn0 = px_block + (c + 1) * 256;
            const __half2* grow = src + (size_t)ch_ld * (HH * WW / 2) + (pxn0 >> 1);
            unsigned dst = (unsigned)__cvta_generic_to_shared(
                               &sm[(c + 1) & 1][ch_ld * SMP + seg_ld]);
            #pragma unroll
            for (int q = 0; q < 4; q++)
                asm volatile("cp.async.cg.shared.global [%0], [%1], 16;" ::
                             "r"(dst + q * 128),
                             "l"((const void*)(grow + ((seg_ld + q * 64) >> 1))) : "memory");
            asm volatile("cp.async.commit_group;" ::: "memory");
            asm volatile("cp.async.wait_group 1;" ::: "memory");   // chunk c done
        } else {
            asm volatile("cp.async.wait_group 0;" ::: "memory");
        }
        __syncthreads();

        const __half* smc = sm[c & 1];
        int px0 = px_block + c * 256;
        int pxw = warp * 32;
        #pragma unroll
        for (int nt = 0; nt < 4; nt++) {
            int pxn = pxw + nt * 8;
            unsigned b0a, b1a, b0b, b1b;
            unsigned a0 = (unsigned)__cvta_generic_to_shared(
                              &smc[(lane & 15) * SMP + pxn]);
            unsigned a1 = (unsigned)__cvta_generic_to_shared(
                              &smc[(16 + (lane & 15)) * SMP + pxn]);
            asm volatile("ldmatrix.sync.aligned.m8n8.x2.trans.shared.b16 {%0,%1}, [%2];"
                         : "=r"(b0a), "=r"(b1a) : "r"(a0));
            asm volatile("ldmatrix.sync.aligned.m8n8.x2.trans.shared.b16 {%0,%1}, [%2];"
                         : "=r"(b0b), "=r"(b1b) : "r"(a1));

            #pragma unroll
            for (int ot = 0; ot < 2; ot++) {
                float d0 = 0.f, d1 = 0.f, d2 = 0.f, d3 = 0.f;
                asm volatile(
                    "mma.sync.aligned.m16n8k16.row.col.f32.f16.f16.f32 "
                    "{%0,%1,%2,%3}, {%4,%5,%6,%7}, {%8,%9}, {%0,%1,%2,%3};"
                    : "+f"(d0), "+f"(d1), "+f"(d2), "+f"(d3)
                    : "r"(Af[0][ot][0]), "r"(Af[0][ot][1]),
                      "r"(Af[0][ot][2]), "r"(Af[0][ot][3]),
                      "r"(b0a), "r"(b1a));
                asm volatile(
                    "mma.sync.aligned.m16n8k16.row.col.f32.f16.f16.f32 "
                    "{%0,%1,%2,%3}, {%4,%5,%6,%7}, {%8,%9}, {%0,%1,%2,%3};"
                    : "+f"(d0), "+f"(d1), "+f"(d2), "+f"(d3)
                    : "r"(Af[1][ot][0]), "r"(Af[1][ot][1]),
                      "r"(Af[1][ot][2]), "r"(Af[1][ot][3]),
                      "r"(b0b), "r"(b1b));

                int px = px0 + pxn + 2 * tg;
                int o0 = ot * 16 + g;
                *(float2*)(ob + (size_t)o0 * (HH * WW) + px)       = make_float2(d0, d1);
                *(float2*)(ob + (size_t)(o0 + 8) * (HH * WW) + px) = make_float2(d2, d3);
            }
        }
        __syncthreads();
    }
}

// Pad so ncu (our launch #4) profiles morph next round: per call m,x,p ->
// overall launch #6 = call-2 morph.
__global__ void pad_kernel() {}

// ---------------------------------------------------------------------------
extern "C" void kernel_launch(void* const* d_in, const int* in_sizes, int n_in,
                              void* d_out, int out_size) {
    const float* x  = (const float*)d_in[0];
    const float* c  = (const float*)d_in[1];
    const float* fd = (const float*)d_in[2];
    const float* fe = (const float*)d_in[3];
    const float* wt = (const float*)d_in[4];
    float* out = (float*)d_out;

    dim3 g1(WW / TO, HH / TO, NB * CCH);   // (4, 4, 512)
    morph_kernel<<<g1, 256>>>(x, c, fd, fe);

    dim3 g2(32, NB);                       // 2048 px per block
    mix_mma_kernel<<<g2, 256>>>(wt, out);

    pad_kernel<<<1, 32>>>();
}